// round 10
// baseline (speedup 1.0000x reference)
#include <cuda_runtime.h>
#include <cuda_fp16.h>
#include <math.h>

// ---------------- problem-size constants ----------------
#define MAXN 100000
#define MAXE 1200000
#define F_IN  64
#define F_HID 64
#define F_OUT 16
#define SCAN_B 256

// ---------------- device scratch (zero at load; re-zeroed at end of agg2) ----
__device__ __half g_y_h[MAXN * F_HID];   // x @ W1, fp16
__device__ __half g_h_h[MAXN * F_HID];   // relu layer-1 output, fp16
__device__ __half g_z_h[MAXN * F_OUT];   // h @ W2, fp16
__device__ int    g_deg[MAXN];           // out-degree by row (for dinv)
__device__ int    g_cnt[MAXN];           // in-degree by col (CSR counts)
__device__ float  g_dinv[MAXN];
__device__ int    g_start[MAXN];         // CSR row_ptr
__device__ int    g_cursor[MAXN];        // fill cursors
__device__ int    g_total;               // global CSR allocation cursor
__device__ int2   g_edge[MAXE];          // packed (src, coef bits), bucketed by col

// ---------------- kernels ----------------

// Fused kernel #1: blocks [0, GB) run gemm1 (y = x @ W1 via HMMA);
// blocks [GB, GB+HB) run the degree histogram. The two are independent and
// bound by different resources (tensor/latency vs L2 atomics).
__global__ __launch_bounds__(256) void hist_gemm1_kernel(const int* __restrict__ ei, int E,
                                                         const float* __restrict__ x,
                                                         const float* __restrict__ W,
                                                         int N, int GB) {
    __shared__ __half W1t[64 * 72];    // W1 transposed: W1t[n][k]
    int tid  = threadIdx.x;

    if (blockIdx.x >= GB) {
        // ---- histogram part ----
        int e = (blockIdx.x - GB) * 256 + tid;
        if (e < E) {
            atomicAdd(&g_deg[ei[e]], 1);
            atomicAdd(&g_cnt[ei[E + e]], 1);
        }
        return;
    }

    // ---- gemm1 part ----
    int lane = tid & 31;
    int warp = tid >> 5;

    for (int i = tid; i < 4096; i += 256) {
        int k = i >> 6, n = i & 63;
        W1t[n * 72 + k] = __float2half(W[i]);
    }
    __syncthreads();

    int row0 = blockIdx.x * 128 + warp * 16;
    int r  = lane >> 2;        // 0..7 fragment row
    int kq = (lane & 3) * 2;   // fragment k offset
    int gr0 = row0 + r;
    int gr1 = row0 + r + 8;
    int sr0 = min(gr0, N - 1);
    int sr1 = min(gr1, N - 1);

    unsigned a[4][4];
#pragma unroll
    for (int kc = 0; kc < 4; kc++) {
        int k0 = kc * 16;
        float2 f0 = *reinterpret_cast<const float2*>(&x[(size_t)sr0 * 64 + k0 + kq]);
        float2 f1 = *reinterpret_cast<const float2*>(&x[(size_t)sr1 * 64 + k0 + kq]);
        float2 f2 = *reinterpret_cast<const float2*>(&x[(size_t)sr0 * 64 + k0 + kq + 8]);
        float2 f3 = *reinterpret_cast<const float2*>(&x[(size_t)sr1 * 64 + k0 + kq + 8]);
        __half2 h0 = __floats2half2_rn(f0.x, f0.y);
        __half2 h1 = __floats2half2_rn(f1.x, f1.y);
        __half2 h2 = __floats2half2_rn(f2.x, f2.y);
        __half2 h3 = __floats2half2_rn(f3.x, f3.y);
        a[kc][0] = *reinterpret_cast<unsigned*>(&h0);
        a[kc][1] = *reinterpret_cast<unsigned*>(&h1);
        a[kc][2] = *reinterpret_cast<unsigned*>(&h2);
        a[kc][3] = *reinterpret_cast<unsigned*>(&h3);
    }

    float acc[8][4];
#pragma unroll
    for (int nt = 0; nt < 8; nt++)
#pragma unroll
        for (int j = 0; j < 4; j++) acc[nt][j] = 0.f;

#pragma unroll
    for (int kc = 0; kc < 4; kc++) {
        int k0 = kc * 16;
#pragma unroll
        for (int nt = 0; nt < 8; nt++) {
            int n = nt * 8 + r;
            unsigned b0 = *reinterpret_cast<unsigned*>(&W1t[n * 72 + k0 + kq]);
            unsigned b1 = *reinterpret_cast<unsigned*>(&W1t[n * 72 + k0 + kq + 8]);
            asm volatile(
                "mma.sync.aligned.m16n8k16.row.col.f32.f16.f16.f32 "
                "{%0,%1,%2,%3}, {%4,%5,%6,%7}, {%8,%9}, {%0,%1,%2,%3};"
                : "+f"(acc[nt][0]), "+f"(acc[nt][1]), "+f"(acc[nt][2]), "+f"(acc[nt][3])
                : "r"(a[kc][0]), "r"(a[kc][1]), "r"(a[kc][2]), "r"(a[kc][3]),
                  "r"(b0), "r"(b1));
        }
    }

#pragma unroll
    for (int nt = 0; nt < 8; nt++) {
        int col = nt * 8 + (lane & 3) * 2;
        __half2 p0 = __floats2half2_rn(acc[nt][0], acc[nt][1]);
        __half2 p1 = __floats2half2_rn(acc[nt][2], acc[nt][3]);
        if (gr0 < N) *reinterpret_cast<__half2*>(&g_y_h[(size_t)gr0 * 64 + col]) = p0;
        if (gr1 < N) *reinterpret_cast<__half2*>(&g_y_h[(size_t)gr1 * 64 + col]) = p1;
    }
}

// CSR allocation: block-local inclusive scan of cnt + one global atomicAdd
// per block for the base. Also computes dinv.
__global__ __launch_bounds__(SCAN_B) void alloc_kernel(int N) {
    __shared__ int s[SCAN_B];
    __shared__ int base_sm;
    int t = threadIdx.x;
    int i = blockIdx.x * SCAN_B + t;
    int v = (i < N) ? g_cnt[i] : 0;
    s[t] = v;
    if (i < N) g_dinv[i] = rsqrtf((float)(g_deg[i] + 1));
    __syncthreads();
    for (int off = 1; off < SCAN_B; off <<= 1) {
        int u = (t >= off) ? s[t - off] : 0;
        __syncthreads();
        s[t] += u;
        __syncthreads();
    }
    if (t == SCAN_B - 1) base_sm = atomicAdd(&g_total, s[t]);
    __syncthreads();
    if (i < N) {
        int st = base_sm + s[t] - v;
        g_start[i] = st;
        g_cursor[i] = st;
    }
}

// Fill CSR: packed (src, coef) records bucketed by col.
__global__ void fill_kernel(const int* __restrict__ ei, int E) {
    int e = blockIdx.x * blockDim.x + threadIdx.x;
    if (e < E) {
        int r = ei[e];
        int c = ei[E + e];
        float coef = g_dinv[r] * g_dinv[c];
        int pos = atomicAdd(&g_cursor[c], 1);
        g_edge[pos] = make_int2(r, __float_as_int(coef));
    }
}

// Layer-1 aggregation: pure CSR gather + self loop + bias + relu -> h fp16.
// One warp per node; 16 edges per iteration (4 slots x 4-wide batch with
// zero-coef padding) -> typically ONE latency chain per node.
__global__ __launch_bounds__(256) void agg1_kernel(const float* __restrict__ b1, int N) {
    int tid = threadIdx.x;
    int warp = (blockIdx.x * blockDim.x + tid) >> 5;
    if (warp >= N) return;
    int lane = tid & 31;
    int slot = lane >> 3;     // 0..3 neighbor slot
    int q = lane & 7;         // uint4 (8-half) chunk within 128B row

    int start = g_start[warp];
    int cnt = g_cnt[warp];

    float a[8];
#pragma unroll
    for (int i = 0; i < 8; i++) a[i] = 0.f;

    const uint4* yrows = reinterpret_cast<const uint4*>(g_y_h);
    const int2 zedge = make_int2(0, 0);   // coef-0 padding: gathers row 0, adds 0
    for (int j = slot; j < cnt; j += 16) {
        int2 e0 = g_edge[start + j];
        int2 e1 = (j + 4  < cnt) ? g_edge[start + j + 4]  : zedge;
        int2 e2 = (j + 8  < cnt) ? g_edge[start + j + 8]  : zedge;
        int2 e3 = (j + 12 < cnt) ? g_edge[start + j + 12] : zedge;
        uint4 v0 = yrows[(size_t)e0.x * 8 + q];
        uint4 v1 = yrows[(size_t)e1.x * 8 + q];
        uint4 v2 = yrows[(size_t)e2.x * 8 + q];
        uint4 v3 = yrows[(size_t)e3.x * 8 + q];
        float c0 = __int_as_float(e0.y);
        float c1 = __int_as_float(e1.y);
        float c2 = __int_as_float(e2.y);
        float c3 = __int_as_float(e3.y);
        float2 f;
        f = __half22float2(*reinterpret_cast<__half2*>(&v0.x)); a[0] += c0 * f.x; a[1] += c0 * f.y;
        f = __half22float2(*reinterpret_cast<__half2*>(&v0.y)); a[2] += c0 * f.x; a[3] += c0 * f.y;
        f = __half22float2(*reinterpret_cast<__half2*>(&v0.z)); a[4] += c0 * f.x; a[5] += c0 * f.y;
        f = __half22float2(*reinterpret_cast<__half2*>(&v0.w)); a[6] += c0 * f.x; a[7] += c0 * f.y;
        f = __half22float2(*reinterpret_cast<__half2*>(&v1.x)); a[0] += c1 * f.x; a[1] += c1 * f.y;
        f = __half22float2(*reinterpret_cast<__half2*>(&v1.y)); a[2] += c1 * f.x; a[3] += c1 * f.y;
        f = __half22float2(*reinterpret_cast<__half2*>(&v1.z)); a[4] += c1 * f.x; a[5] += c1 * f.y;
        f = __half22float2(*reinterpret_cast<__half2*>(&v1.w)); a[6] += c1 * f.x; a[7] += c1 * f.y;
        f = __half22float2(*reinterpret_cast<__half2*>(&v2.x)); a[0] += c2 * f.x; a[1] += c2 * f.y;
        f = __half22float2(*reinterpret_cast<__half2*>(&v2.y)); a[2] += c2 * f.x; a[3] += c2 * f.y;
        f = __half22float2(*reinterpret_cast<__half2*>(&v2.z)); a[4] += c2 * f.x; a[5] += c2 * f.y;
        f = __half22float2(*reinterpret_cast<__half2*>(&v2.w)); a[6] += c2 * f.x; a[7] += c2 * f.y;
        f = __half22float2(*reinterpret_cast<__half2*>(&v3.x)); a[0] += c3 * f.x; a[1] += c3 * f.y;
        f = __half22float2(*reinterpret_cast<__half2*>(&v3.y)); a[2] += c3 * f.x; a[3] += c3 * f.y;
        f = __half22float2(*reinterpret_cast<__half2*>(&v3.z)); a[4] += c3 * f.x; a[5] += c3 * f.y;
        f = __half22float2(*reinterpret_cast<__half2*>(&v3.w)); a[6] += c3 * f.x; a[7] += c3 * f.y;
    }
#pragma unroll
    for (int i = 0; i < 8; i++) {
        a[i] += __shfl_xor_sync(0xffffffffu, a[i], 8);
        a[i] += __shfl_xor_sync(0xffffffffu, a[i], 16);
    }

    if (lane < 8) {
        float di = g_dinv[warp];
        float s = di * di;
        uint4 yv = yrows[(size_t)warp * 8 + q];
        float2 y0 = __half22float2(*reinterpret_cast<__half2*>(&yv.x));
        float2 y1 = __half22float2(*reinterpret_cast<__half2*>(&yv.y));
        float2 y2 = __half22float2(*reinterpret_cast<__half2*>(&yv.z));
        float2 y3 = __half22float2(*reinterpret_cast<__half2*>(&yv.w));
        float4 bb0 = reinterpret_cast<const float4*>(b1)[q * 2];
        float4 bb1 = reinterpret_cast<const float4*>(b1)[q * 2 + 1];
        __half2 p0 = __floats2half2_rn(fmaxf(a[0] + s * y0.x + bb0.x, 0.f),
                                       fmaxf(a[1] + s * y0.y + bb0.y, 0.f));
        __half2 p1 = __floats2half2_rn(fmaxf(a[2] + s * y1.x + bb0.z, 0.f),
                                       fmaxf(a[3] + s * y1.y + bb0.w, 0.f));
        __half2 p2 = __floats2half2_rn(fmaxf(a[4] + s * y2.x + bb1.x, 0.f),
                                       fmaxf(a[5] + s * y2.y + bb1.y, 0.f));
        __half2 p3 = __floats2half2_rn(fmaxf(a[6] + s * y3.x + bb1.z, 0.f),
                                       fmaxf(a[7] + s * y3.y + bb1.w, 0.f));
        uint4 o;
        o.x = *reinterpret_cast<unsigned*>(&p0);
        o.y = *reinterpret_cast<unsigned*>(&p1);
        o.z = *reinterpret_cast<unsigned*>(&p2);
        o.w = *reinterpret_cast<unsigned*>(&p3);
        reinterpret_cast<uint4*>(g_h_h)[(size_t)warp * 8 + q] = o;
    }
}

// z = h @ W2 ([N,64] fp16 @ [64,16]) via HMMA m16n8k16 -> fp16.
__global__ __launch_bounds__(256) void gemm2_kernel(const float* __restrict__ W2, int N) {
    __shared__ __half hs[128 * 72];
    __shared__ __half W2t[16 * 72];    // transposed: W2t[n][k]
    int tid  = threadIdx.x;
    int lane = tid & 31;
    int warp = tid >> 5;

    for (int i = tid; i < 1024; i += 256) {
        int k = i >> 4, n = i & 15;
        W2t[n * 72 + k] = __float2half(W2[i]);
    }

    int row0 = blockIdx.x * 128;
    for (int i = tid; i < 1024; i += 256) {
        int r = i >> 3, c = i & 7;
        int gr = row0 + r;
        uint4 v = (gr < N) ? reinterpret_cast<const uint4*>(g_h_h)[(size_t)gr * 8 + c]
                           : make_uint4(0u, 0u, 0u, 0u);
        *reinterpret_cast<uint4*>(&hs[r * 72 + c * 8]) = v;
    }
    __syncthreads();

    int rbase = warp * 16;
    int r  = lane >> 2;
    int kq = (lane & 3) * 2;

    float acc[2][4];
#pragma unroll
    for (int nt = 0; nt < 2; nt++)
#pragma unroll
        for (int j = 0; j < 4; j++) acc[nt][j] = 0.f;

#pragma unroll
    for (int kc = 0; kc < 4; kc++) {
        int k0 = kc * 16;
        unsigned a0 = *reinterpret_cast<unsigned*>(&hs[(rbase + r)     * 72 + k0 + kq]);
        unsigned a1 = *reinterpret_cast<unsigned*>(&hs[(rbase + r + 8) * 72 + k0 + kq]);
        unsigned a2 = *reinterpret_cast<unsigned*>(&hs[(rbase + r)     * 72 + k0 + kq + 8]);
        unsigned a3 = *reinterpret_cast<unsigned*>(&hs[(rbase + r + 8) * 72 + k0 + kq + 8]);
#pragma unroll
        for (int nt = 0; nt < 2; nt++) {
            int n = nt * 8 + r;
            unsigned b0 = *reinterpret_cast<unsigned*>(&W2t[n * 72 + k0 + kq]);
            unsigned b1 = *reinterpret_cast<unsigned*>(&W2t[n * 72 + k0 + kq + 8]);
            asm volatile(
                "mma.sync.aligned.m16n8k16.row.col.f32.f16.f16.f32 "
                "{%0,%1,%2,%3}, {%4,%5,%6,%7}, {%8,%9}, {%0,%1,%2,%3};"
                : "+f"(acc[nt][0]), "+f"(acc[nt][1]), "+f"(acc[nt][2]), "+f"(acc[nt][3])
                : "r"(a0), "r"(a1), "r"(a2), "r"(a3), "r"(b0), "r"(b1));
        }
    }

    int gr0 = row0 + rbase + r;
    int gr1 = gr0 + 8;
#pragma unroll
    for (int nt = 0; nt < 2; nt++) {
        int col = nt * 8 + (lane & 3) * 2;
        __half2 p0 = __floats2half2_rn(acc[nt][0], acc[nt][1]);
        __half2 p1 = __floats2half2_rn(acc[nt][2], acc[nt][3]);
        if (gr0 < N) *reinterpret_cast<__half2*>(&g_z_h[(size_t)gr0 * 16 + col]) = p0;
        if (gr1 < N) *reinterpret_cast<__half2*>(&g_z_h[(size_t)gr1 * 16 + col]) = p1;
    }
}

// Layer-2 aggregation + self loop + bias + log_softmax -> out.
// 16 edges per iteration (8 slots x 2-wide batch, zero-coef padding).
// Also re-zeroes g_deg/g_cnt/g_total for the next graph replay.
__global__ __launch_bounds__(256) void agg2_kernel(const float* __restrict__ b2,
                                                   float* __restrict__ out, int N) {
    int tid = threadIdx.x;
    int warp = (blockIdx.x * blockDim.x + tid) >> 5;
    if (warp >= N) return;
    int lane = tid & 31;

    int start = g_start[warp];
    int cnt = g_cnt[warp];
    __syncwarp();
    if (lane == 0) { g_deg[warp] = 0; g_cnt[warp] = 0; }
    if (warp == 0 && lane == 1) g_total = 0;

    int slot = lane >> 2;    // 0..7 neighbor slot
    int q = lane & 3;        // uint2 (4-half) chunk within 32B row

    float a[4];
#pragma unroll
    for (int i = 0; i < 4; i++) a[i] = 0.f;

    const uint2* zrows = reinterpret_cast<const uint2*>(g_z_h);
    const int2 zedge = make_int2(0, 0);
    for (int j = slot; j < cnt; j += 16) {
        int2 e0 = g_edge[start + j];
        int2 e1 = (j + 8 < cnt) ? g_edge[start + j + 8] : zedge;
        uint2 v0 = zrows[(size_t)e0.x * 4 + q];
        uint2 v1 = zrows[(size_t)e1.x * 4 + q];
        float c0 = __int_as_float(e0.y);
        float c1 = __int_as_float(e1.y);
        float2 f;
        f = __half22float2(*reinterpret_cast<__half2*>(&v0.x)); a[0] += c0 * f.x; a[1] += c0 * f.y;
        f = __half22float2(*reinterpret_cast<__half2*>(&v0.y)); a[2] += c0 * f.x; a[3] += c0 * f.y;
        f = __half22float2(*reinterpret_cast<__half2*>(&v1.x)); a[0] += c1 * f.x; a[1] += c1 * f.y;
        f = __half22float2(*reinterpret_cast<__half2*>(&v1.y)); a[2] += c1 * f.x; a[3] += c1 * f.y;
    }
#pragma unroll
    for (int i = 0; i < 4; i++) {
        a[i] += __shfl_xor_sync(0xffffffffu, a[i], 4);
        a[i] += __shfl_xor_sync(0xffffffffu, a[i], 8);
        a[i] += __shfl_xor_sync(0xffffffffu, a[i], 16);
    }

    float di = g_dinv[warp];
    float s = di * di;
    uint2 zv = zrows[(size_t)warp * 4 + q];
    float2 z0 = __half22float2(*reinterpret_cast<__half2*>(&zv.x));
    float2 z1 = __half22float2(*reinterpret_cast<__half2*>(&zv.y));
    float4 bb = reinterpret_cast<const float4*>(b2)[q];
    float4 l;
    l.x = a[0] + s * z0.x + bb.x;
    l.y = a[1] + s * z0.y + bb.y;
    l.z = a[2] + s * z1.x + bb.z;
    l.w = a[3] + s * z1.y + bb.w;

    float m4 = fmaxf(fmaxf(l.x, l.y), fmaxf(l.z, l.w));
    m4 = fmaxf(m4, __shfl_xor_sync(0xffffffffu, m4, 1));
    m4 = fmaxf(m4, __shfl_xor_sync(0xffffffffu, m4, 2));
    float se = __expf(l.x - m4) + __expf(l.y - m4) + __expf(l.z - m4) + __expf(l.w - m4);
    se += __shfl_xor_sync(0xffffffffu, se, 1);
    se += __shfl_xor_sync(0xffffffffu, se, 2);
    float lse = m4 + __logf(se);

    if (lane < 4) {
        float4 o;
        o.x = l.x - lse;
        o.y = l.y - lse;
        o.z = l.z - lse;
        o.w = l.w - lse;
        reinterpret_cast<float4*>(out)[(size_t)warp * 4 + q] = o;
    }
}

// ---------------- launch ----------------
extern "C" void kernel_launch(void* const* d_in, const int* in_sizes, int n_in,
                              void* d_out, int out_size) {
    const float* x  = (const float*)d_in[0];
    const int*   ei = (const int*)d_in[1];   // int32 (JAX x64 disabled)
    const float* W1 = (const float*)d_in[2];
    const float* b1 = (const float*)d_in[3];
    const float* W2 = (const float*)d_in[4];
    const float* b2 = (const float*)d_in[5];
    float*       out = (float*)d_out;

    int N = in_sizes[0] / F_IN;
    int E = in_sizes[1] / 2;
    const int TB = 256;

    int GB = (N + 127) / 128;            // gemm1 blocks
    int HB = (E + TB - 1) / TB;          // hist blocks
    hist_gemm1_kernel<<<GB + HB, TB>>>(ei, E, x, W1, N, GB);

    alloc_kernel<<<(N + SCAN_B - 1) / SCAN_B, SCAN_B>>>(N);
    fill_kernel<<<(E + TB - 1) / TB, TB>>>(ei, E);

    long long a1_threads = (long long)N * 32;
    agg1_kernel<<<(unsigned)((a1_threads + TB - 1) / TB), TB>>>(b1, N);   // launch #4 -> profiled

    gemm2_kernel<<<(N + 127) / 128, TB>>>(W2, N);

    long long a2_threads = (long long)N * 32;
    agg2_kernel<<<(unsigned)((a2_threads + TB - 1) / TB), TB>>>(b2, out, N);
}

// round 12
// speedup vs baseline: 1.0169x; 1.0169x over previous
#include <cuda_runtime.h>
#include <cuda_fp16.h>
#include <math.h>

// ---------------- problem-size constants ----------------
#define MAXN 100000
#define MAXE 1200000
#define F_IN  64
#define F_HID 64
#define F_OUT 16
#define SCAN_B 256

// ---------------- device scratch (zero at load; re-zeroed at end of agg2) ----
__device__ __half g_y_h[MAXN * F_HID];   // x @ W1, fp16
__device__ __half g_h_h[MAXN * F_HID];   // relu layer-1 output, fp16
__device__ __half g_z_h[MAXN * F_OUT];   // h @ W2, fp16
__device__ int    g_deg[MAXN];           // out-degree by row (for dinv)
__device__ int    g_cnt[MAXN];           // in-degree by col (CSR counts)
__device__ float  g_dinv[MAXN];
__device__ int    g_start[MAXN];         // CSR row_ptr
__device__ int    g_cursor[MAXN];        // fill cursors
__device__ int    g_total;               // global CSR allocation cursor
__device__ int2   g_edge[MAXE];          // packed (src, half2 coef bits), by col

// ---------------- helpers ----------------
__device__ __forceinline__ unsigned hfma2_u(unsigned v, unsigned c, unsigned a) {
    __half2 r = __hfma2(*reinterpret_cast<__half2*>(&v),
                        *reinterpret_cast<__half2*>(&c),
                        *reinterpret_cast<__half2*>(&a));
    return *reinterpret_cast<unsigned*>(&r);
}
__device__ __forceinline__ unsigned hadd2_u(unsigned a, unsigned b) {
    __half2 r = __hadd2(*reinterpret_cast<__half2*>(&a),
                        *reinterpret_cast<__half2*>(&b));
    return *reinterpret_cast<unsigned*>(&r);
}
__device__ __forceinline__ float2 h2f2(unsigned a) {
    return __half22float2(*reinterpret_cast<__half2*>(&a));
}

// ---------------- kernels ----------------

// Fused kernel #1: blocks [0, GB) run gemm1 (y = x @ W1 via HMMA);
// blocks [GB, GB+HB) run the degree histogram.
__global__ __launch_bounds__(256) void hist_gemm1_kernel(const int* __restrict__ ei, int E,
                                                         const float* __restrict__ x,
                                                         const float* __restrict__ W,
                                                         int N, int GB) {
    __shared__ __half W1t[64 * 72];    // W1 transposed: W1t[n][k]
    int tid  = threadIdx.x;

    if (blockIdx.x >= GB) {
        int e = (blockIdx.x - GB) * 256 + tid;
        if (e < E) {
            atomicAdd(&g_deg[ei[e]], 1);
            atomicAdd(&g_cnt[ei[E + e]], 1);
        }
        return;
    }

    int lane = tid & 31;
    int warp = tid >> 5;

    for (int i = tid; i < 4096; i += 256) {
        int k = i >> 6, n = i & 63;
        W1t[n * 72 + k] = __float2half(W[i]);
    }
    __syncthreads();

    int row0 = blockIdx.x * 128 + warp * 16;
    int r  = lane >> 2;
    int kq = (lane & 3) * 2;
    int gr0 = row0 + r;
    int gr1 = row0 + r + 8;
    int sr0 = min(gr0, N - 1);
    int sr1 = min(gr1, N - 1);

    unsigned a[4][4];
#pragma unroll
    for (int kc = 0; kc < 4; kc++) {
        int k0 = kc * 16;
        float2 f0 = *reinterpret_cast<const float2*>(&x[(size_t)sr0 * 64 + k0 + kq]);
        float2 f1 = *reinterpret_cast<const float2*>(&x[(size_t)sr1 * 64 + k0 + kq]);
        float2 f2 = *reinterpret_cast<const float2*>(&x[(size_t)sr0 * 64 + k0 + kq + 8]);
        float2 f3 = *reinterpret_cast<const float2*>(&x[(size_t)sr1 * 64 + k0 + kq + 8]);
        __half2 h0 = __floats2half2_rn(f0.x, f0.y);
        __half2 h1 = __floats2half2_rn(f1.x, f1.y);
        __half2 h2 = __floats2half2_rn(f2.x, f2.y);
        __half2 h3 = __floats2half2_rn(f3.x, f3.y);
        a[kc][0] = *reinterpret_cast<unsigned*>(&h0);
        a[kc][1] = *reinterpret_cast<unsigned*>(&h1);
        a[kc][2] = *reinterpret_cast<unsigned*>(&h2);
        a[kc][3] = *reinterpret_cast<unsigned*>(&h3);
    }

    float acc[8][4];
#pragma unroll
    for (int nt = 0; nt < 8; nt++)
#pragma unroll
        for (int j = 0; j < 4; j++) acc[nt][j] = 0.f;

#pragma unroll
    for (int kc = 0; kc < 4; kc++) {
        int k0 = kc * 16;
#pragma unroll
        for (int nt = 0; nt < 8; nt++) {
            int n = nt * 8 + r;
            unsigned b0 = *reinterpret_cast<unsigned*>(&W1t[n * 72 + k0 + kq]);
            unsigned b1 = *reinterpret_cast<unsigned*>(&W1t[n * 72 + k0 + kq + 8]);
            asm volatile(
                "mma.sync.aligned.m16n8k16.row.col.f32.f16.f16.f32 "
                "{%0,%1,%2,%3}, {%4,%5,%6,%7}, {%8,%9}, {%0,%1,%2,%3};"
                : "+f"(acc[nt][0]), "+f"(acc[nt][1]), "+f"(acc[nt][2]), "+f"(acc[nt][3])
                : "r"(a[kc][0]), "r"(a[kc][1]), "r"(a[kc][2]), "r"(a[kc][3]),
                  "r"(b0), "r"(b1));
        }
    }

#pragma unroll
    for (int nt = 0; nt < 8; nt++) {
        int col = nt * 8 + (lane & 3) * 2;
        __half2 p0 = __floats2half2_rn(acc[nt][0], acc[nt][1]);
        __half2 p1 = __floats2half2_rn(acc[nt][2], acc[nt][3]);
        if (gr0 < N) *reinterpret_cast<__half2*>(&g_y_h[(size_t)gr0 * 64 + col]) = p0;
        if (gr1 < N) *reinterpret_cast<__half2*>(&g_y_h[(size_t)gr1 * 64 + col]) = p1;
    }
}

// CSR allocation: block-local inclusive scan of cnt + one global atomicAdd
// per block for the base. Also computes dinv.
__global__ __launch_bounds__(SCAN_B) void alloc_kernel(int N) {
    __shared__ int s[SCAN_B];
    __shared__ int base_sm;
    int t = threadIdx.x;
    int i = blockIdx.x * SCAN_B + t;
    int v = (i < N) ? g_cnt[i] : 0;
    s[t] = v;
    if (i < N) g_dinv[i] = rsqrtf((float)(g_deg[i] + 1));
    __syncthreads();
    for (int off = 1; off < SCAN_B; off <<= 1) {
        int u = (t >= off) ? s[t - off] : 0;
        __syncthreads();
        s[t] += u;
        __syncthreads();
    }
    if (t == SCAN_B - 1) base_sm = atomicAdd(&g_total, s[t]);
    __syncthreads();
    if (i < N) {
        int st = base_sm + s[t] - v;
        g_start[i] = st;
        g_cursor[i] = st;
    }
}

// Fill CSR: packed (src, half2(coef,coef) bits) records bucketed by col.
__global__ void fill_kernel(const int* __restrict__ ei, int E) {
    int e = blockIdx.x * blockDim.x + threadIdx.x;
    if (e < E) {
        int r = ei[e];
        int c = ei[E + e];
        float coef = g_dinv[r] * g_dinv[c];
        __half2 ch = __floats2half2_rn(coef, coef);
        int pos = atomicAdd(&g_cursor[c], 1);
        g_edge[pos] = make_int2(r, *reinterpret_cast<int*>(&ch));
    }
}

// Layer-1 aggregation: pure CSR gather with fp16 HFMA2 accumulation
// + self loop + bias + relu (f32) -> h fp16.
// One warp per node; 16 edges per iteration (4 slots x 4-wide batch,
// zero-coef padding).
__global__ __launch_bounds__(256) void agg1_kernel(const float* __restrict__ b1, int N) {
    int tid = threadIdx.x;
    int warp = (blockIdx.x * blockDim.x + tid) >> 5;
    if (warp >= N) return;
    int lane = tid & 31;
    int slot = lane >> 3;     // 0..3 neighbor slot
    int q = lane & 7;         // uint4 (8-half) chunk within 128B row

    int start = g_start[warp];
    int cnt = g_cnt[warp];

    unsigned acc[4] = {0u, 0u, 0u, 0u};   // 4x half2 accumulators (8 halves)

    const uint4* yrows = reinterpret_cast<const uint4*>(g_y_h);
    const int2 zedge = make_int2(0, 0);   // half2(0,0) coef padding
    for (int j = slot; j < cnt; j += 16) {
        int2 e0 = g_edge[start + j];
        int2 e1 = (j + 4  < cnt) ? g_edge[start + j + 4]  : zedge;
        int2 e2 = (j + 8  < cnt) ? g_edge[start + j + 8]  : zedge;
        int2 e3 = (j + 12 < cnt) ? g_edge[start + j + 12] : zedge;
        uint4 v0 = yrows[(size_t)e0.x * 8 + q];
        uint4 v1 = yrows[(size_t)e1.x * 8 + q];
        uint4 v2 = yrows[(size_t)e2.x * 8 + q];
        uint4 v3 = yrows[(size_t)e3.x * 8 + q];
        unsigned c0 = (unsigned)e0.y;
        unsigned c1 = (unsigned)e1.y;
        unsigned c2 = (unsigned)e2.y;
        unsigned c3 = (unsigned)e3.y;
        acc[0] = hfma2_u(v0.x, c0, acc[0]);
        acc[1] = hfma2_u(v0.y, c0, acc[1]);
        acc[2] = hfma2_u(v0.z, c0, acc[2]);
        acc[3] = hfma2_u(v0.w, c0, acc[3]);
        acc[0] = hfma2_u(v1.x, c1, acc[0]);
        acc[1] = hfma2_u(v1.y, c1, acc[1]);
        acc[2] = hfma2_u(v1.z, c1, acc[2]);
        acc[3] = hfma2_u(v1.w, c1, acc[3]);
        acc[0] = hfma2_u(v2.x, c2, acc[0]);
        acc[1] = hfma2_u(v2.y, c2, acc[1]);
        acc[2] = hfma2_u(v2.z, c2, acc[2]);
        acc[3] = hfma2_u(v2.w, c2, acc[3]);
        acc[0] = hfma2_u(v3.x, c3, acc[0]);
        acc[1] = hfma2_u(v3.y, c3, acc[1]);
        acc[2] = hfma2_u(v3.z, c3, acc[2]);
        acc[3] = hfma2_u(v3.w, c3, acc[3]);
    }
    // reduce across the 4 slots in fp16
#pragma unroll
    for (int i = 0; i < 4; i++) {
        acc[i] = hadd2_u(acc[i], __shfl_xor_sync(0xffffffffu, acc[i], 8));
        acc[i] = hadd2_u(acc[i], __shfl_xor_sync(0xffffffffu, acc[i], 16));
    }

    if (lane < 8) {
        float2 a0 = h2f2(acc[0]);
        float2 a1 = h2f2(acc[1]);
        float2 a2 = h2f2(acc[2]);
        float2 a3 = h2f2(acc[3]);
        float di = g_dinv[warp];
        float s = di * di;
        uint4 yv = yrows[(size_t)warp * 8 + q];
        float2 y0 = h2f2(yv.x);
        float2 y1 = h2f2(yv.y);
        float2 y2 = h2f2(yv.z);
        float2 y3 = h2f2(yv.w);
        float4 bb0 = reinterpret_cast<const float4*>(b1)[q * 2];
        float4 bb1 = reinterpret_cast<const float4*>(b1)[q * 2 + 1];
        __half2 p0 = __floats2half2_rn(fmaxf(a0.x + s * y0.x + bb0.x, 0.f),
                                       fmaxf(a0.y + s * y0.y + bb0.y, 0.f));
        __half2 p1 = __floats2half2_rn(fmaxf(a1.x + s * y1.x + bb0.z, 0.f),
                                       fmaxf(a1.y + s * y1.y + bb0.w, 0.f));
        __half2 p2 = __floats2half2_rn(fmaxf(a2.x + s * y2.x + bb1.x, 0.f),
                                       fmaxf(a2.y + s * y2.y + bb1.y, 0.f));
        __half2 p3 = __floats2half2_rn(fmaxf(a3.x + s * y3.x + bb1.z, 0.f),
                                       fmaxf(a3.y + s * y3.y + bb1.w, 0.f));
        uint4 o;
        o.x = *reinterpret_cast<unsigned*>(&p0);
        o.y = *reinterpret_cast<unsigned*>(&p1);
        o.z = *reinterpret_cast<unsigned*>(&p2);
        o.w = *reinterpret_cast<unsigned*>(&p3);
        reinterpret_cast<uint4*>(g_h_h)[(size_t)warp * 8 + q] = o;
    }
}

// z = h @ W2 ([N,64] fp16 @ [64,16]) via HMMA m16n8k16 -> fp16.
__global__ __launch_bounds__(256) void gemm2_kernel(const float* __restrict__ W2, int N) {
    __shared__ __half hs[128 * 72];
    __shared__ __half W2t[16 * 72];    // transposed: W2t[n][k]
    int tid  = threadIdx.x;
    int lane = tid & 31;
    int warp = tid >> 5;

    for (int i = tid; i < 1024; i += 256) {
        int k = i >> 4, n = i & 15;
        W2t[n * 72 + k] = __float2half(W2[i]);
    }

    int row0 = blockIdx.x * 128;
    for (int i = tid; i < 1024; i += 256) {
        int r = i >> 3, c = i & 7;
        int gr = row0 + r;
        uint4 v = (gr < N) ? reinterpret_cast<const uint4*>(g_h_h)[(size_t)gr * 8 + c]
                           : make_uint4(0u, 0u, 0u, 0u);
        *reinterpret_cast<uint4*>(&hs[r * 72 + c * 8]) = v;
    }
    __syncthreads();

    int rbase = warp * 16;
    int r  = lane >> 2;
    int kq = (lane & 3) * 2;

    float acc[2][4];
#pragma unroll
    for (int nt = 0; nt < 2; nt++)
#pragma unroll
        for (int j = 0; j < 4; j++) acc[nt][j] = 0.f;

#pragma unroll
    for (int kc = 0; kc < 4; kc++) {
        int k0 = kc * 16;
        unsigned a0 = *reinterpret_cast<unsigned*>(&hs[(rbase + r)     * 72 + k0 + kq]);
        unsigned a1 = *reinterpret_cast<unsigned*>(&hs[(rbase + r + 8) * 72 + k0 + kq]);
        unsigned a2 = *reinterpret_cast<unsigned*>(&hs[(rbase + r)     * 72 + k0 + kq + 8]);
        unsigned a3 = *reinterpret_cast<unsigned*>(&hs[(rbase + r + 8) * 72 + k0 + kq + 8]);
#pragma unroll
        for (int nt = 0; nt < 2; nt++) {
            int n = nt * 8 + r;
            unsigned b0 = *reinterpret_cast<unsigned*>(&W2t[n * 72 + k0 + kq]);
            unsigned b1 = *reinterpret_cast<unsigned*>(&W2t[n * 72 + k0 + kq + 8]);
            asm volatile(
                "mma.sync.aligned.m16n8k16.row.col.f32.f16.f16.f32 "
                "{%0,%1,%2,%3}, {%4,%5,%6,%7}, {%8,%9}, {%0,%1,%2,%3};"
                : "+f"(acc[nt][0]), "+f"(acc[nt][1]), "+f"(acc[nt][2]), "+f"(acc[nt][3])
                : "r"(a0), "r"(a1), "r"(a2), "r"(a3), "r"(b0), "r"(b1));
        }
    }

    int gr0 = row0 + rbase + r;
    int gr1 = gr0 + 8;
#pragma unroll
    for (int nt = 0; nt < 2; nt++) {
        int col = nt * 8 + (lane & 3) * 2;
        __half2 p0 = __floats2half2_rn(acc[nt][0], acc[nt][1]);
        __half2 p1 = __floats2half2_rn(acc[nt][2], acc[nt][3]);
        if (gr0 < N) *reinterpret_cast<__half2*>(&g_z_h[(size_t)gr0 * 16 + col]) = p0;
        if (gr1 < N) *reinterpret_cast<__half2*>(&g_z_h[(size_t)gr1 * 16 + col]) = p1;
    }
}

// Layer-2 aggregation (fp16 HFMA2 accumulate) + self loop + bias +
// log_softmax (f32) -> out. Re-zeroes g_deg/g_cnt/g_total for next replay.
__global__ __launch_bounds__(256) void agg2_kernel(const float* __restrict__ b2,
                                                   float* __restrict__ out, int N) {
    int tid = threadIdx.x;
    int warp = (blockIdx.x * blockDim.x + tid) >> 5;
    if (warp >= N) return;
    int lane = tid & 31;

    int start = g_start[warp];
    int cnt = g_cnt[warp];
    __syncwarp();
    if (lane == 0) { g_deg[warp] = 0; g_cnt[warp] = 0; }
    if (warp == 0 && lane == 1) g_total = 0;

    int slot = lane >> 2;    // 0..7 neighbor slot
    int q = lane & 3;        // uint2 (4-half) chunk within 32B row

    unsigned acc[2] = {0u, 0u};   // 2x half2 accumulators (4 halves)

    const uint2* zrows = reinterpret_cast<const uint2*>(g_z_h);
    const int2 zedge = make_int2(0, 0);
    for (int j = slot; j < cnt; j += 16) {
        int2 e0 = g_edge[start + j];
        int2 e1 = (j + 8 < cnt) ? g_edge[start + j + 8] : zedge;
        uint2 v0 = zrows[(size_t)e0.x * 4 + q];
        uint2 v1 = zrows[(size_t)e1.x * 4 + q];
        unsigned c0 = (unsigned)e0.y;
        unsigned c1 = (unsigned)e1.y;
        acc[0] = hfma2_u(v0.x, c0, acc[0]);
        acc[1] = hfma2_u(v0.y, c0, acc[1]);
        acc[0] = hfma2_u(v1.x, c1, acc[0]);
        acc[1] = hfma2_u(v1.y, c1, acc[1]);
    }
#pragma unroll
    for (int i = 0; i < 2; i++) {
        acc[i] = hadd2_u(acc[i], __shfl_xor_sync(0xffffffffu, acc[i], 4));
        acc[i] = hadd2_u(acc[i], __shfl_xor_sync(0xffffffffu, acc[i], 8));
        acc[i] = hadd2_u(acc[i], __shfl_xor_sync(0xffffffffu, acc[i], 16));
    }
    float2 a0 = h2f2(acc[0]);
    float2 a1 = h2f2(acc[1]);

    float di = g_dinv[warp];
    float s = di * di;
    uint2 zv = zrows[(size_t)warp * 4 + q];
    float2 z0 = h2f2(zv.x);
    float2 z1 = h2f2(zv.y);
    float4 bb = reinterpret_cast<const float4*>(b2)[q];
    float4 l;
    l.x = a0.x + s * z0.x + bb.x;
    l.y = a0.y + s * z0.y + bb.y;
    l.z = a1.x + s * z1.x + bb.z;
    l.w = a1.y + s * z1.y + bb.w;

    float m4 = fmaxf(fmaxf(l.x, l.y), fmaxf(l.z, l.w));
    m4 = fmaxf(m4, __shfl_xor_sync(0xffffffffu, m4, 1));
    m4 = fmaxf(m4, __shfl_xor_sync(0xffffffffu, m4, 2));
    float se = __expf(l.x - m4) + __expf(l.y - m4) + __expf(l.z - m4) + __expf(l.w - m4);
    se += __shfl_xor_sync(0xffffffffu, se, 1);
    se += __shfl_xor_sync(0xffffffffu, se, 2);
    float lse = m4 + __logf(se);

    if (lane < 4) {
        float4 o;
        o.x = l.x - lse;
        o.y = l.y - lse;
        o.z = l.z - lse;
        o.w = l.w - lse;
        reinterpret_cast<float4*>(out)[(size_t)warp * 4 + q] = o;
    }
}

// ---------------- launch ----------------
extern "C" void kernel_launch(void* const* d_in, const int* in_sizes, int n_in,
                              void* d_out, int out_size) {
    const float* x  = (const float*)d_in[0];
    const int*   ei = (const int*)d_in[1];   // int32 (JAX x64 disabled)
    const float* W1 = (const float*)d_in[2];
    const float* b1 = (const float*)d_in[3];
    const float* W2 = (const float*)d_in[4];
    const float* b2 = (const float*)d_in[5];
    float*       out = (float*)d_out;

    int N = in_sizes[0] / F_IN;
    int E = in_sizes[1] / 2;
    const int TB = 256;

    int GB = (N + 127) / 128;            // gemm1 blocks
    int HB = (E + TB - 1) / TB;          // hist blocks
    hist_gemm1_kernel<<<GB + HB, TB>>>(ei, E, x, W1, N, GB);

    alloc_kernel<<<(N + SCAN_B - 1) / SCAN_B, SCAN_B>>>(N);
    fill_kernel<<<(E + TB - 1) / TB, TB>>>(ei, E);

    long long a1_threads = (long long)N * 32;
    agg1_kernel<<<(unsigned)((a1_threads + TB - 1) / TB), TB>>>(b1, N);   // launch #4 -> profiled

    gemm2_kernel<<<(N + 127) / 128, TB>>>(W2, N);

    long long a2_threads = (long long)N * 32;
    agg2_kernel<<<(unsigned)((a2_threads + TB - 1) / TB), TB>>>(b2, out, N);
}